// round 14
// baseline (speedup 1.0000x reference)
#include <cuda_runtime.h>
#include <cuda_fp16.h>
#include <math.h>
#include <stdint.h>

#define BB 4096
#define LAT 256
#define HH 512
#define AA 64
#define LL 128
#define NG3 1536         // gate layout: 64 groups x [r8|z8|n8]
#define M2 ((long)(LL - 1) * BB)   // 520192

// ---- scratch (static device globals; ~4.0 GB) ----
__device__ half  g_Hd[(size_t)(LL - 1) * BB * HH];     // h_t fp16, slots t=1..127
__device__ half  g_P1[(size_t)(LL - 1) * BB * HH];
__device__ half  g_P2[(size_t)(LL - 1) * BB * AA];
__device__ half  g_X[(size_t)(LL - 1) * BB * AA];
__device__ half  g_Gx[(size_t)(LL - 1) * BB * NG3];    // precomputed x-gates (+bias)
__device__ float g_h32a[(size_t)BB * HH];
__device__ float g_h32b[(size_t)BB * HH];
__device__ half  g_H0[(size_t)BB * HH];
__device__ half  g_t1[(size_t)BB * HH];
__device__ half  g_t2[(size_t)BB * HH];
__device__ half  g_L[(size_t)BB * LAT];
__device__ half  g_Wh3[(size_t)NG3 * HH];              // interleaved Whh
__device__ half  g_Wix[(size_t)NG3 * AA];              // interleaved Wih (r,z,nx)
__device__ half  g_Wd1[HH * LAT];
__device__ half  g_Wd2[HH * HH];
__device__ half  g_Wd3[HH * HH];
__device__ half  g_Wm1[HH * HH];
__device__ half  g_Wm2[AA * HH];
__device__ half  g_Wm3[AA * AA];
__device__ float g_gxbias[NG3];
__device__ float g_bhhn[HH];

// ============================================================
// helpers
// ============================================================
__device__ __forceinline__ uint32_t smem_u32(const void* p) {
    uint32_t a;
    asm("{ .reg .u64 t; cvta.to.shared.u64 t, %1; cvt.u32.u64 %0, t; }" : "=r"(a) : "l"(p));
    return a;
}
__device__ __forceinline__ void cpa16(uint32_t dst, const void* src) {
    asm volatile("cp.async.cg.shared.global [%0], [%1], 16;" :: "r"(dst), "l"(src));
}
__device__ __forceinline__ void cpa_commit() {
    asm volatile("cp.async.commit_group;" ::: "memory");
}
__device__ __forceinline__ void cpa_wait0() {
    asm volatile("cp.async.wait_group 0;" ::: "memory");
}
__device__ __forceinline__ float sigf(float x) { return 1.0f / (1.0f + expf(-x)); }

__device__ __forceinline__ void mma16(float d[4], const uint32_t a[4], const uint32_t b[2]) {
    asm volatile(
        "mma.sync.aligned.m16n8k16.row.col.f32.f16.f16.f32 "
        "{%0,%1,%2,%3},{%4,%5,%6,%7},{%8,%9},{%0,%1,%2,%3};"
        : "+f"(d[0]), "+f"(d[1]), "+f"(d[2]), "+f"(d[3])
        : "r"(a[0]), "r"(a[1]), "r"(a[2]), "r"(a[3]), "r"(b[0]), "r"(b[1]));
}
__device__ __forceinline__ void ldsm_x4(uint32_t r[4], uint32_t addr) {
    asm volatile("ldmatrix.sync.aligned.m8n8.x4.shared.b16 {%0,%1,%2,%3}, [%4];"
                 : "=r"(r[0]), "=r"(r[1]), "=r"(r[2]), "=r"(r[3]) : "r"(addr));
}
__device__ __forceinline__ void ldsm_x2(uint32_t r[2], uint32_t addr) {
    asm volatile("ldmatrix.sync.aligned.m8n8.x2.shared.b16 {%0,%1}, [%2];"
                 : "=r"(r[0]), "=r"(r[1]) : "r"(addr));
}

// ============================================================
// Setup kernels
// ============================================================
__global__ void fill_bos_out(float* __restrict__ out) {
    int idx = blockIdx.x * blockDim.x + threadIdx.x;
    int b = idx >> 6, a = idx & 63;
    out[(size_t)b * (LL * AA) + a] = (a == 0) ? 16.0f : -16.0f;
}
__global__ void build_X(const float* __restrict__ target, half* __restrict__ X) {
    size_t idx = (size_t)blockIdx.x * blockDim.x + threadIdx.x;
    int a = (int)(idx & 63);
    size_t row = idx >> 6;
    int trow = (int)(row >> 12);
    int b = (int)(row & 4095);
    float v;
    if (trow == 0) v = (a == 0) ? 16.0f : -16.0f;
    else           v = target[((size_t)b << 13) + (size_t)trow * AA + a];
    X[idx] = __float2half_rn(v);
}
__global__ void tohalf(const float* __restrict__ src, half* __restrict__ dst, int n) {
    int i = blockIdx.x * blockDim.x + threadIdx.x;
    if (i < n) dst[i] = __float2half_rn(src[i]);
}
__global__ void build_Wh3(const float* __restrict__ Whh, half* __restrict__ w) {
    int i = blockIdx.x * blockDim.x + threadIdx.x;
    if (i >= NG3 * HH) return;
    int k = i & 511, c = i >> 9;
    int g = c / 24, r = c % 24;
    int type = r >> 3, j = 8 * g + (r & 7);
    w[i] = __float2half_rn(Whh[(size_t)(type * 512 + j) * HH + k]);
}
__global__ void build_Wix(const float* __restrict__ Wih, half* __restrict__ w) {
    int i = blockIdx.x * blockDim.x + threadIdx.x;
    if (i >= NG3 * AA) return;
    int k = i & 63, c = i >> 6;
    int g = c / 24, r = c % 24;
    int type = r >> 3, j = 8 * g + (r & 7);
    w[i] = __float2half_rn(Wih[(type * 512 + j) * AA + k]);
}
__global__ void build_gxbias(const float* __restrict__ bih, const float* __restrict__ bhh,
                             float* __restrict__ bc) {
    int c = blockIdx.x * blockDim.x + threadIdx.x;
    if (c >= NG3) return;
    int g = c / 24, r = c % 24;
    int type = r >> 3, j = 8 * g + (r & 7);
    float v;
    if (type == 0)      v = bih[j] + bhh[j];
    else if (type == 1) v = bih[512 + j] + bhh[512 + j];
    else                v = bih[1024 + j];
    bc[c] = v;
}
__global__ void build_bhhn(const float* __restrict__ bhh, float* __restrict__ bn) {
    int j = blockIdx.x * blockDim.x + threadIdx.x;
    if (j < HH) bn[j] = bhh[1024 + j];
}

// ============================================================
// dec_tile: one BM=128 x BN=64 GEMM tile, fp16 in, fp32 acc.
// 256 threads, warp grid 4M x 2N (warp tile 32x32), MI=2, NI=4.
// 2-stage cp.async, ldmatrix, one __syncthreads per chunk.
// EPI: 0 = fp16 store; 1 = tanh->fp16; 2 = f32 + fp16; 3 = scatter f32.
// ============================================================
template <int EPI>
__device__ __forceinline__ void dec_tile(
    long m0, int n0,
    const half* __restrict__ A_g, long lda,
    const half* __restrict__ B_g, int K,
    const float* __restrict__ bias,
    float* __restrict__ Cf, long ldc,
    half* __restrict__ Ch)
{
    constexpr int SS = 72;
    constexpr int MI = 2;
    constexpr int NI = 4;
    constexpr int ABYT = 128 * SS * 2;
    constexpr int BBYT = 64 * SS * 2;
    constexpr int BUF = ABYT + BBYT;

    extern __shared__ char smem[];
    const uint32_t sb = smem_u32(smem);

    const int tid = threadIdx.x;
    const int wid = tid >> 5, lane = tid & 31;
    const int wm = wid & 3, wn = wid >> 2;     // 4M x 2N
    const int gr = lane >> 2, tq = lane & 3;
    const int aro = (lane & 7) + ((lane >> 3) & 1) * 8;
    const int aco = (lane >> 4) * 8;
    const int bro = ((lane >> 4) & 1) * 8 + (lane & 7);
    const int bko = ((lane >> 3) & 1) * 8;

    const int nc = K >> 6;

    float acc[MI][NI][4];
#pragma unroll
    for (int mi = 0; mi < MI; ++mi)
#pragma unroll
        for (int ni = 0; ni < NI; ++ni)
#pragma unroll
            for (int q = 0; q < 4; ++q) acc[mi][ni][q] = 0.0f;

    auto load_chunk = [&](int ch) {
        const int k0 = ch << 6;
        const uint32_t base = sb + (ch & 1) * BUF;
#pragma unroll
        for (int it = 0; it < 4; ++it) {
            int e = tid + it * 256;
            int row = e >> 3, seg = e & 7;
            cpa16(base + (uint32_t)(row * SS + seg * 8) * 2,
                  A_g + (m0 + row) * lda + k0 + seg * 8);
        }
#pragma unroll
        for (int it = 0; it < 2; ++it) {
            int e = tid + it * 256;
            int row = e >> 3, seg = e & 7;
            cpa16(base + ABYT + (uint32_t)(row * SS + seg * 8) * 2,
                  B_g + (long)(n0 + row) * K + k0 + seg * 8);
        }
    };

    load_chunk(0); cpa_commit();

    for (int ch = 0; ch < nc; ++ch) {
        cpa_wait0();                 // chunk ch resident
        __syncthreads();             // all warps done computing ch-1
        if (ch + 1 < nc) load_chunk(ch + 1);
        cpa_commit();

        const uint32_t aBase = sb + (ch & 1) * BUF;
        const uint32_t bBase = aBase + ABYT;

#pragma unroll
        for (int k16 = 0; k16 < 4; ++k16) {
            const int kk = k16 * 16;
            uint32_t af[MI][4], bf[NI][2];
#pragma unroll
            for (int mi = 0; mi < MI; ++mi)
                ldsm_x4(af[mi], aBase + (uint32_t)((wm * 32 + mi * 16 + aro) * SS + kk + aco) * 2);
#pragma unroll
            for (int n2 = 0; n2 < NI / 2; ++n2)
                ldsm_x4(&bf[2 * n2][0], bBase + (uint32_t)((wn * 32 + n2 * 16 + bro) * SS + kk + bko) * 2);
#pragma unroll
            for (int mi = 0; mi < MI; ++mi)
#pragma unroll
                for (int ni = 0; ni < NI; ++ni)
                    mma16(acc[mi][ni], af[mi], bf[ni]);
        }
    }

#pragma unroll
    for (int mi = 0; mi < MI; ++mi) {
#pragma unroll
        for (int ni = 0; ni < NI; ++ni) {
            const int col = n0 + wn * 32 + ni * 8 + 2 * tq;
            const long mA = m0 + wm * 32 + mi * 16 + gr;
            float2 bc = *(const float2*)(bias + col);
            float v0 = acc[mi][ni][0] + bc.x;
            float v1 = acc[mi][ni][1] + bc.y;
            float v2 = acc[mi][ni][2] + bc.x;
            float v3 = acc[mi][ni][3] + bc.y;

            if (EPI <= 2) {
                if (EPI == 1) { v0 = tanhf(v0); v1 = tanhf(v1); v2 = tanhf(v2); v3 = tanhf(v3); }
                if (EPI == 2) {
                    *(float2*)(Cf + mA * ldc + col) = make_float2(v0, v1);
                    *(float2*)(Cf + (mA + 8) * ldc + col) = make_float2(v2, v3);
                }
                __half2 p0 = __floats2half2_rn(v0, v1);
                __half2 p1 = __floats2half2_rn(v2, v3);
                *(uint32_t*)(Ch + mA * ldc + col) = *(uint32_t*)&p0;
                *(uint32_t*)(Ch + (mA + 8) * ldc + col) = *(uint32_t*)&p1;
            } else {
                long t1_ = (mA >> 12) + 1, b1_ = mA & 4095;
                long t2_ = ((mA + 8) >> 12) + 1, b2_ = (mA + 8) & 4095;
                *(float2*)(Cf + b1_ * (LL * AA) + t1_ * AA + col) = make_float2(v0, v1);
                *(float2*)(Cf + b2_ * (LL * AA) + t2_ * AA + col) = make_float2(v2, v3);
            }
        }
    }
}

// standalone GEMM wrapper (mrow0 = global row offset), BN=64
template <int EPI>
__global__ void __launch_bounds__(256, 3)
mma_gemm(long mrow0,
         const half* __restrict__ A_g, long lda,
         const half* __restrict__ B_g, int K,
         const float* __restrict__ bias,
         float* __restrict__ Cf, long ldc,
         half* __restrict__ Ch)
{
    dec_tile<EPI>(mrow0 + (long)blockIdx.y * 128, blockIdx.x * 64,
                  A_g, lda, B_g, K, bias, Cf, ldc, Ch);
}

// ============================================================
// gru_tile: one 128x96 tile of Ghh = h @ Wh3^T + fused GRU epilogue.
// 256 threads, warp grid 2M x 4N (warp tile 64x24), MI=4, NI=3.
// ============================================================
__device__ __forceinline__ void gru_tile(
    const half* __restrict__ A_g,      // hprev fp16 [BB,512]
    const half* __restrict__ gx,       // Gx slab [BB,1536]
    const float* __restrict__ hprev32,
    float* __restrict__ hnew32,
    half* __restrict__ hnew16,
    int mbk, int nbk)
{
    constexpr int SS = 72;
    constexpr int MI = 4;
    constexpr int NI = 3;
    constexpr int ABYT = 128 * SS * 2;
    constexpr int BBYT = 96 * SS * 2;
    constexpr int BUF = ABYT + BBYT;
    constexpr int nc = HH >> 6;

    extern __shared__ char smem[];
    const uint32_t sb = smem_u32(smem);

    const int tid = threadIdx.x;
    const int wid = tid >> 5, lane = tid & 31;
    const int wm = wid & 1, wn = wid >> 1;     // 2M x 4N
    const int gr = lane >> 2, tq = lane & 3;
    const int aro = (lane & 7) + ((lane >> 3) & 1) * 8;
    const int aco = (lane >> 4) * 8;
    const int bro = ((lane >> 4) & 1) * 8 + (lane & 7);
    const int bko = ((lane >> 3) & 1) * 8;
    const int b2ro = 16 + (lane & 7);
    const int b2ko = ((lane >> 3) & 1) * 8;

    const long m0 = (long)mbk * 128;
    const int  n0 = nbk * 96;
    const half* B_g = g_Wh3;

    float acc[MI][NI][4];
#pragma unroll
    for (int mi = 0; mi < MI; ++mi)
#pragma unroll
        for (int ni = 0; ni < NI; ++ni)
#pragma unroll
            for (int q = 0; q < 4; ++q) acc[mi][ni][q] = 0.0f;

    auto load_chunk = [&](int ch) {
        const int k0 = ch << 6;
        const uint32_t base = sb + (ch & 1) * BUF;
#pragma unroll
        for (int it = 0; it < 4; ++it) {
            int e = tid + it * 256;
            int row = e >> 3, seg = e & 7;
            cpa16(base + (uint32_t)(row * SS + seg * 8) * 2,
                  A_g + (m0 + row) * (long)HH + k0 + seg * 8);
        }
#pragma unroll
        for (int it = 0; it < 3; ++it) {
            int e = tid + it * 256;
            int row = e >> 3, seg = e & 7;
            cpa16(base + ABYT + (uint32_t)(row * SS + seg * 8) * 2,
                  B_g + (long)(n0 + row) * HH + k0 + seg * 8);
        }
    };

    load_chunk(0); cpa_commit();

    for (int ch = 0; ch < nc; ++ch) {
        cpa_wait0();
        __syncthreads();
        if (ch + 1 < nc) load_chunk(ch + 1);
        cpa_commit();

        const uint32_t aBase = sb + (ch & 1) * BUF;
        const uint32_t bBase = aBase + ABYT;

#pragma unroll
        for (int k16 = 0; k16 < 4; ++k16) {
            const int kk = k16 * 16;
            uint32_t af[MI][4], bf[NI][2];
#pragma unroll
            for (int mi = 0; mi < MI; ++mi)
                ldsm_x4(af[mi], aBase + (uint32_t)((wm * 64 + mi * 16 + aro) * SS + kk + aco) * 2);
            ldsm_x4(&bf[0][0], bBase + (uint32_t)((wn * 24 + bro) * SS + kk + bko) * 2);
            ldsm_x2(&bf[2][0], bBase + (uint32_t)((wn * 24 + b2ro) * SS + kk + b2ko) * 2);
#pragma unroll
            for (int mi = 0; mi < MI; ++mi)
#pragma unroll
                for (int ni = 0; ni < NI; ++ni)
                    mma16(acc[mi][ni], af[mi], bf[ni]);
        }
    }

    const int jb = 8 * (4 * nbk + wn);
    const int j0 = jb + 2 * tq;
    const float2 bn2 = *(const float2*)(g_bhhn + j0);

#pragma unroll
    for (int mi = 0; mi < MI; ++mi) {
#pragma unroll
        for (int h2 = 0; h2 < 2; ++h2) {
            const long m = m0 + wm * 64 + mi * 16 + gr + h2 * 8;
            const half* gp = gx + m * NG3 + n0 + wn * 24 + 2 * tq;
            float2 gxr = __half22float2(*(const __half2*)(gp));
            float2 gxz = __half22float2(*(const __half2*)(gp + 8));
            float2 gxn = __half22float2(*(const __half2*)(gp + 16));
            float2 hp = *(const float2*)(hprev32 + m * HH + j0);
            const int q0 = h2 * 2, q1 = q0 + 1;

            float r0 = sigf(acc[mi][0][q0] + gxr.x);
            float r1 = sigf(acc[mi][0][q1] + gxr.y);
            float z0 = sigf(acc[mi][1][q0] + gxz.x);
            float z1 = sigf(acc[mi][1][q1] + gxz.y);
            float nv0 = tanhf(gxn.x + r0 * (acc[mi][2][q0] + bn2.x));
            float nv1 = tanhf(gxn.y + r1 * (acc[mi][2][q1] + bn2.y));
            float h0 = (1.0f - z0) * nv0 + z0 * hp.x;
            float h1 = (1.0f - z1) * nv1 + z1 * hp.y;

            *(float2*)(hnew32 + m * HH + j0) = make_float2(h0, h1);
            __half2 ph = __floats2half2_rn(h0, h1);
            *(uint32_t*)(hnew16 + m * HH + j0) = *(uint32_t*)&ph;
        }
    }
}

// ============================================================
// Fused step: gru (512 CTAs) + pipelined decoder/Gx tail-fill.
// bid: [0,512) gru(t) | [512,768) Wm1(t-2 slab) | [768,800) Wm2
//      [800,1568) Gx(t+3 slab) | [1568,1600) Wm3
// ============================================================
__global__ void __launch_bounds__(256, 3)
step_fused(int t,
           const half* __restrict__ hin,
           half* __restrict__ hout,
           const float* __restrict__ hprev32,
           float* __restrict__ hnew32,
           const float* __restrict__ bm1,
           const float* __restrict__ bm2,
           const float* __restrict__ bm3,
           float* __restrict__ out)
{
    const int bid = blockIdx.x;
    if (bid < 512) {
        gru_tile(hin, g_Gx + (size_t)(t - 1) * BB * NG3, hprev32, hnew32, hout,
                 bid >> 4, bid & 15);
    } else if (bid < 768) {
        if (t < 2) return;
        int i = bid - 512;                    // 32 m x 8 n
        dec_tile<1>((long)(t - 2) * BB + (long)(i >> 3) * 128, (i & 7) * 64,
                    g_Hd, HH, g_Wm1, HH, bm1, nullptr, HH, g_P1);
    } else if (bid < 800) {
        if (t < 3) return;
        int i = bid - 768;                    // 32 m x 1 n
        dec_tile<1>((long)(t - 3) * BB + (long)i * 128, 0,
                    g_P1, HH, g_Wm2, HH, bm2, nullptr, AA, g_P2);
    } else if (bid < 1568) {
        if (t < 2 || t > 123) return;
        int i = bid - 800;                    // 32 m x 24 n
        dec_tile<0>((long)(t + 3) * BB + (long)(i / 24) * 128, (i % 24) * 64,
                    g_X, AA, g_Wix, AA, g_gxbias, nullptr, NG3, g_Gx);
    } else {
        if (t < 4) return;
        int i = bid - 1568;                   // 32 m x 1 n
        dec_tile<3>((long)(t - 4) * BB + (long)i * 128, 0,
                    g_P2, AA, g_Wm3, AA, bm3, out, 0, nullptr);
    }
}

// ============================================================
// Orchestration
// ============================================================
extern "C" void kernel_launch(void* const* d_in, const int* in_sizes, int n_in,
                              void* d_out, int out_size)
{
    const float* latent = (const float*)d_in[0];
    const float* target = (const float*)d_in[1];
    const float* Wd1 = (const float*)d_in[2];
    const float* bd1 = (const float*)d_in[3];
    const float* Wd2 = (const float*)d_in[4];
    const float* bd2 = (const float*)d_in[5];
    const float* Wd3 = (const float*)d_in[6];
    const float* bd3 = (const float*)d_in[7];
    const float* Wih = (const float*)d_in[8];
    const float* Whh = (const float*)d_in[9];
    const float* bih = (const float*)d_in[10];
    const float* bhh = (const float*)d_in[11];
    const float* Wm1 = (const float*)d_in[12];
    const float* bm1 = (const float*)d_in[13];
    const float* Wm2 = (const float*)d_in[14];
    const float* bm2 = (const float*)d_in[15];
    const float* Wm3 = (const float*)d_in[16];
    const float* bm3 = (const float*)d_in[17];
    float* out = (float*)d_out;

#define SYM(v, s) cudaGetSymbolAddress((void**)&v, s)
    half *Hd, *P1, *P2, *X, *Gx, *H0, *t1, *t2, *L;
    half *Wh3, *Wix, *Wd1h, *Wd2h, *Wd3h, *Wm1h, *Wm2h, *Wm3h;
    float *h32a, *h32b, *gxbias, *bhhn;
    SYM(Hd, g_Hd); SYM(P1, g_P1); SYM(P2, g_P2); SYM(X, g_X); SYM(Gx, g_Gx);
    SYM(H0, g_H0); SYM(t1, g_t1); SYM(t2, g_t2); SYM(L, g_L);
    SYM(Wh3, g_Wh3); SYM(Wix, g_Wix);
    SYM(Wd1h, g_Wd1); SYM(Wd2h, g_Wd2); SYM(Wd3h, g_Wd3);
    SYM(Wm1h, g_Wm1); SYM(Wm2h, g_Wm2); SYM(Wm3h, g_Wm3);
    SYM(h32a, g_h32a); SYM(h32b, g_h32b); SYM(gxbias, g_gxbias); SYM(bhhn, g_bhhn);
#undef SYM

    constexpr int SMD = 2 * (128 * 72 * 2 + 64 * 72 * 2);    // 55296
    constexpr int SMG = 2 * (128 * 72 * 2 + 96 * 72 * 2);    // 64512
    constexpr int SMF = SMG;
    cudaFuncSetAttribute(mma_gemm<0>, cudaFuncAttributeMaxDynamicSharedMemorySize, SMD);
    cudaFuncSetAttribute(mma_gemm<1>, cudaFuncAttributeMaxDynamicSharedMemorySize, SMD);
    cudaFuncSetAttribute(mma_gemm<2>, cudaFuncAttributeMaxDynamicSharedMemorySize, SMD);
    cudaFuncSetAttribute(mma_gemm<3>, cudaFuncAttributeMaxDynamicSharedMemorySize, SMD);
    cudaFuncSetAttribute(step_fused,  cudaFuncAttributeMaxDynamicSharedMemorySize, SMF);

    // ---- setup (4th launch = fused step for ncu profiling) ----
    build_X<<<(int)((M2 * AA) / 256), 256>>>(target, X);                       // 1
    build_Wh3<<<(NG3 * HH + 255) / 256, 256>>>(Whh, Wh3);                      // 2
    build_bhhn<<<(HH + 255) / 256, 256>>>(bhh, bhhn);                          // 3
    // 4: dummy fused step (profiling target). Every output slab it writes is
    // recomputed by a later real launch in this same call.
    step_fused<<<1600, 256, SMF>>>(10, Hd + (size_t)8 * BB * HH,
                                   Hd + (size_t)9 * BB * HH,
                                   h32a, h32b, bm1, bm2, bm3, out);

    build_Wix<<<(NG3 * AA + 255) / 256, 256>>>(Wih, Wix);
    build_gxbias<<<(NG3 + 255) / 256, 256>>>(bih, bhh, gxbias);
    fill_bos_out<<<(BB * AA) / 256, 256>>>(out);
    tohalf<<<(BB * LAT + 255) / 256, 256>>>(latent, L, BB * LAT);
    tohalf<<<(HH * LAT + 255) / 256, 256>>>(Wd1, Wd1h, HH * LAT);
    tohalf<<<(HH * HH + 255) / 256, 256>>>(Wd2, Wd2h, HH * HH);
    tohalf<<<(HH * HH + 255) / 256, 256>>>(Wd3, Wd3h, HH * HH);
    tohalf<<<(HH * HH + 255) / 256, 256>>>(Wm1, Wm1h, HH * HH);
    tohalf<<<(AA * HH + 255) / 256, 256>>>(Wm2, Wm2h, AA * HH);
    tohalf<<<(AA * AA + 255) / 256, 256>>>(Wm3, Wm3h, AA * AA);

    // ---- Gx slabs 0..4 upfront (steps 1-5); rest pipelined in-step ----
    mma_gemm<0><<<dim3(NG3 / 64, 5 * BB / 128), 256, SMD>>>(
        0, X, AA, Wix, AA, gxbias, nullptr, NG3, Gx);

    // ---- h0 = Wd3(tanh(Wd2(tanh(Wd1(latent))))) ----
    mma_gemm<1><<<dim3(HH / 64, BB / 128), 256, SMD>>>(
        0, L, LAT, Wd1h, LAT, bd1, nullptr, HH, t1);
    mma_gemm<1><<<dim3(HH / 64, BB / 128), 256, SMD>>>(
        0, t1, HH, Wd2h, HH, bd2, nullptr, HH, t2);
    mma_gemm<2><<<dim3(HH / 64, BB / 128), 256, SMD>>>(
        0, t2, HH, Wd3h, HH, bd3, h32a, HH, H0);

    // ---- sequential GRU with fused decoder/Gx tail-fill ----
    float* hp32 = h32a;
    float* hn32 = h32b;
    for (int t = 1; t < LL; ++t) {
        const half* hin = (t == 1) ? H0 : Hd + (size_t)(t - 2) * BB * HH;
        step_fused<<<1600, 256, SMF>>>(t, hin,
                                       Hd + (size_t)(t - 1) * BB * HH,
                                       hp32, hn32, bm1, bm2, bm3, out);
        float* tmp = hp32; hp32 = hn32; hn32 = tmp;
    }

    // ---- drain: Wm1 slab 126; Wm2 slabs 125-126; Wm3 slabs 124-126 ----
    mma_gemm<1><<<dim3(HH / 64, BB / 128), 256, SMD>>>(
        (long)126 * BB, Hd, HH, Wm1h, HH, bm1, nullptr, HH, P1);
    mma_gemm<1><<<dim3(1, 2 * BB / 128), 256, SMD>>>(
        (long)125 * BB, P1, HH, Wm2h, HH, bm2, nullptr, AA, P2);
    mma_gemm<3><<<dim3(1, 3 * BB / 128), 256, SMD>>>(
        (long)124 * BB, P2, AA, Wm3h, AA, bm3, out, 0, nullptr);
}

// round 16
// speedup vs baseline: 1.6153x; 1.6153x over previous
#include <cuda_runtime.h>
#include <cuda_fp16.h>
#include <math.h>
#include <stdint.h>

#define BB 4096
#define LAT 256
#define HH 512
#define AA 64
#define LL 128
#define NG3 1536         // gate layout: 64 groups x [r8|z8|n8]
#define M2 ((long)(LL - 1) * BB)   // 520192

// ---- scratch (static device globals; ~4.0 GB) ----
__device__ half  g_Hd[(size_t)(LL - 1) * BB * HH];     // h_t fp16, slots t=1..127
__device__ half  g_P1[(size_t)(LL - 1) * BB * HH];
__device__ half  g_P2[(size_t)(LL - 1) * BB * AA];
__device__ half  g_X[(size_t)(LL - 1) * BB * AA];
__device__ half  g_Gx[(size_t)(LL - 1) * BB * NG3];    // precomputed x-gates (+bias)
__device__ float g_h32a[(size_t)BB * HH];
__device__ float g_h32b[(size_t)BB * HH];
__device__ half  g_H0[(size_t)BB * HH];
__device__ half  g_t1[(size_t)BB * HH];
__device__ half  g_t2[(size_t)BB * HH];
__device__ half  g_L[(size_t)BB * LAT];
__device__ half  g_Wh3[(size_t)NG3 * HH];              // interleaved Whh
__device__ half  g_Wix[(size_t)NG3 * AA];              // interleaved Wih (r,z,nx)
__device__ half  g_Wd1[HH * LAT];
__device__ half  g_Wd2[HH * HH];
__device__ half  g_Wd3[HH * HH];
__device__ half  g_Wm1[HH * HH];
__device__ half  g_Wm2[AA * HH];
__device__ half  g_Wm3[AA * AA];
__device__ float g_gxbias[NG3];
__device__ float g_bhhn[HH];

// ============================================================
// helpers
// ============================================================
__device__ __forceinline__ uint32_t smem_u32(const void* p) {
    uint32_t a;
    asm("{ .reg .u64 t; cvta.to.shared.u64 t, %1; cvt.u32.u64 %0, t; }" : "=r"(a) : "l"(p));
    return a;
}
__device__ __forceinline__ void cpa16(uint32_t dst, const void* src) {
    asm volatile("cp.async.cg.shared.global [%0], [%1], 16;" :: "r"(dst), "l"(src));
}
__device__ __forceinline__ void cpa_commit() {
    asm volatile("cp.async.commit_group;" ::: "memory");
}
__device__ __forceinline__ void cpa_wait1() {
    asm volatile("cp.async.wait_group 1;" ::: "memory");
}
__device__ __forceinline__ float sigf(float x) { return 1.0f / (1.0f + expf(-x)); }

__device__ __forceinline__ void mma16(float d[4], const uint32_t a[4], const uint32_t b[2]) {
    asm volatile(
        "mma.sync.aligned.m16n8k16.row.col.f32.f16.f16.f32 "
        "{%0,%1,%2,%3},{%4,%5,%6,%7},{%8,%9},{%0,%1,%2,%3};"
        : "+f"(d[0]), "+f"(d[1]), "+f"(d[2]), "+f"(d[3])
        : "r"(a[0]), "r"(a[1]), "r"(a[2]), "r"(a[3]), "r"(b[0]), "r"(b[1]));
}
__device__ __forceinline__ void ldsm_x4(uint32_t r[4], uint32_t addr) {
    asm volatile("ldmatrix.sync.aligned.m8n8.x4.shared.b16 {%0,%1,%2,%3}, [%4];"
                 : "=r"(r[0]), "=r"(r[1]), "=r"(r[2]), "=r"(r[3]) : "r"(addr));
}
__device__ __forceinline__ void ldsm_x2(uint32_t r[2], uint32_t addr) {
    asm volatile("ldmatrix.sync.aligned.m8n8.x2.shared.b16 {%0,%1}, [%2];"
                 : "=r"(r[0]), "=r"(r[1]) : "r"(addr));
}

// ============================================================
// Setup kernels
// ============================================================
__global__ void fill_bos_out(float* __restrict__ out) {
    int idx = blockIdx.x * blockDim.x + threadIdx.x;
    int b = idx >> 6, a = idx & 63;
    out[(size_t)b * (LL * AA) + a] = (a == 0) ? 16.0f : -16.0f;
}
__global__ void build_X(const float* __restrict__ target, half* __restrict__ X) {
    size_t idx = (size_t)blockIdx.x * blockDim.x + threadIdx.x;
    int a = (int)(idx & 63);
    size_t row = idx >> 6;
    int trow = (int)(row >> 12);
    int b = (int)(row & 4095);
    float v;
    if (trow == 0) v = (a == 0) ? 16.0f : -16.0f;
    else           v = target[((size_t)b << 13) + (size_t)trow * AA + a];
    X[idx] = __float2half_rn(v);
}
__global__ void tohalf(const float* __restrict__ src, half* __restrict__ dst, int n) {
    int i = blockIdx.x * blockDim.x + threadIdx.x;
    if (i < n) dst[i] = __float2half_rn(src[i]);
}
__global__ void build_Wh3(const float* __restrict__ Whh, half* __restrict__ w) {
    int i = blockIdx.x * blockDim.x + threadIdx.x;
    if (i >= NG3 * HH) return;
    int k = i & 511, c = i >> 9;
    int g = c / 24, r = c % 24;
    int type = r >> 3, j = 8 * g + (r & 7);
    w[i] = __float2half_rn(Whh[(size_t)(type * 512 + j) * HH + k]);
}
__global__ void build_Wix(const float* __restrict__ Wih, half* __restrict__ w) {
    int i = blockIdx.x * blockDim.x + threadIdx.x;
    if (i >= NG3 * AA) return;
    int k = i & 63, c = i >> 6;
    int g = c / 24, r = c % 24;
    int type = r >> 3, j = 8 * g + (r & 7);
    w[i] = __float2half_rn(Wih[(type * 512 + j) * AA + k]);
}
__global__ void build_gxbias(const float* __restrict__ bih, const float* __restrict__ bhh,
                             float* __restrict__ bc) {
    int c = blockIdx.x * blockDim.x + threadIdx.x;
    if (c >= NG3) return;
    int g = c / 24, r = c % 24;
    int type = r >> 3, j = 8 * g + (r & 7);
    float v;
    if (type == 0)      v = bih[j] + bhh[j];
    else if (type == 1) v = bih[512 + j] + bhh[512 + j];
    else                v = bih[1024 + j];
    bc[c] = v;
}
__global__ void build_bhhn(const float* __restrict__ bhh, float* __restrict__ bn) {
    int j = blockIdx.x * blockDim.x + threadIdx.x;
    if (j < HH) bn[j] = bhh[1024 + j];
}

// ============================================================
// dec_tile: one BM=128 x BN GEMM tile, fp16 in, fp32 acc.
// 512 threads, warp grid 4M x 4N (warp tile 32 x BN/4), MI=2.
// 3-stage cp.async, ldmatrix, one __syncthreads per chunk.
// EPI: 0 = fp16 store; 1 = tanh->fp16; 2 = f32 + fp16; 3 = scatter f32.
// ============================================================
template <int BN, int EPI>
__device__ __forceinline__ void dec_tile(
    long m0, int n0,
    const half* __restrict__ A_g, long lda,
    const half* __restrict__ B_g, int K,
    const float* __restrict__ bias,
    float* __restrict__ Cf, long ldc,
    half* __restrict__ Ch)
{
    constexpr int SS = 72;
    constexpr int MI = 2;
    constexpr int WN = BN / 4;           // 32 or 16
    constexpr int NI = WN / 8;           // 4 or 2
    constexpr int ABYT = 128 * SS * 2;
    constexpr int BBYT = BN * SS * 2;
    constexpr int BUF = ABYT + BBYT;

    extern __shared__ char smem[];
    const uint32_t sb = smem_u32(smem);

    const int tid = threadIdx.x;
    const int wid = tid >> 5, lane = tid & 31;
    const int wm = wid & 3, wn = wid >> 2;
    const int gr = lane >> 2, tq = lane & 3;
    const int aro = (lane & 7) + ((lane >> 3) & 1) * 8;
    const int aco = (lane >> 4) * 8;
    const int bro = ((lane >> 4) & 1) * 8 + (lane & 7);
    const int bko = ((lane >> 3) & 1) * 8;

    const int nc = K >> 6;

    float acc[MI][NI][4];
#pragma unroll
    for (int mi = 0; mi < MI; ++mi)
#pragma unroll
        for (int ni = 0; ni < NI; ++ni)
#pragma unroll
            for (int q = 0; q < 4; ++q) acc[mi][ni][q] = 0.0f;

    auto load_chunk = [&](int ch) {
        const int k0 = ch << 6;
        const uint32_t base = sb + (ch % 3) * BUF;
#pragma unroll
        for (int it = 0; it < 2; ++it) {
            int e = tid + it * 512;
            int row = e >> 3, seg = e & 7;
            cpa16(base + (uint32_t)(row * SS + seg * 8) * 2,
                  A_g + (m0 + row) * lda + k0 + seg * 8);
        }
#pragma unroll
        for (int it = 0; it < BN / 64; ++it) {
            int e = tid + it * 512;
            int row = e >> 3, seg = e & 7;
            cpa16(base + ABYT + (uint32_t)(row * SS + seg * 8) * 2,
                  B_g + (long)(n0 + row) * K + k0 + seg * 8);
        }
    };

    load_chunk(0); cpa_commit();
    if (nc > 1) load_chunk(1);
    cpa_commit();

    for (int ch = 0; ch < nc; ++ch) {
        cpa_wait1();
        __syncthreads();
        if (ch + 2 < nc) load_chunk(ch + 2);
        cpa_commit();

        const uint32_t aBase = sb + (ch % 3) * BUF;
        const uint32_t bBase = aBase + ABYT;

#pragma unroll
        for (int k16 = 0; k16 < 4; ++k16) {
            const int kk = k16 * 16;
            uint32_t af[MI][4], bf[NI][2];
#pragma unroll
            for (int mi = 0; mi < MI; ++mi)
                ldsm_x4(af[mi], aBase + (uint32_t)((wm * 32 + mi * 16 + aro) * SS + kk + aco) * 2);
#pragma unroll
            for (int n2 = 0; n2 < NI / 2; ++n2)
                ldsm_x4(&bf[2 * n2][0], bBase + (uint32_t)((wn * WN + n2 * 16 + bro) * SS + kk + bko) * 2);
#pragma unroll
            for (int mi = 0; mi < MI; ++mi)
#pragma unroll
                for (int ni = 0; ni < NI; ++ni)
                    mma16(acc[mi][ni], af[mi], bf[ni]);
        }
    }

#pragma unroll
    for (int mi = 0; mi < MI; ++mi) {
#pragma unroll
        for (int ni = 0; ni < NI; ++ni) {
            const int col = n0 + wn * WN + ni * 8 + 2 * tq;
            const long mA = m0 + wm * 32 + mi * 16 + gr;
            float2 bc = *(const float2*)(bias + col);
            float v0 = acc[mi][ni][0] + bc.x;
            float v1 = acc[mi][ni][1] + bc.y;
            float v2 = acc[mi][ni][2] + bc.x;
            float v3 = acc[mi][ni][3] + bc.y;

            if (EPI <= 2) {
                if (EPI == 1) { v0 = tanhf(v0); v1 = tanhf(v1); v2 = tanhf(v2); v3 = tanhf(v3); }
                if (EPI == 2) {
                    *(float2*)(Cf + mA * ldc + col) = make_float2(v0, v1);
                    *(float2*)(Cf + (mA + 8) * ldc + col) = make_float2(v2, v3);
                }
                __half2 p0 = __floats2half2_rn(v0, v1);
                __half2 p1 = __floats2half2_rn(v2, v3);
                *(uint32_t*)(Ch + mA * ldc + col) = *(uint32_t*)&p0;
                *(uint32_t*)(Ch + (mA + 8) * ldc + col) = *(uint32_t*)&p1;
            } else {
                long t1_ = (mA >> 12) + 1, b1_ = mA & 4095;
                long t2_ = ((mA + 8) >> 12) + 1, b2_ = (mA + 8) & 4095;
                *(float2*)(Cf + b1_ * (LL * AA) + t1_ * AA + col) = make_float2(v0, v1);
                *(float2*)(Cf + b2_ * (LL * AA) + t2_ * AA + col) = make_float2(v2, v3);
            }
        }
    }
}

// standalone GEMM wrapper (mrow0 = global row offset)
template <int BN, int EPI>
__global__ void __launch_bounds__(512, 2)
mma_gemm(long mrow0,
         const half* __restrict__ A_g, long lda,
         const half* __restrict__ B_g, int K,
         const float* __restrict__ bias,
         float* __restrict__ Cf, long ldc,
         half* __restrict__ Ch)
{
    dec_tile<BN, EPI>(mrow0 + (long)blockIdx.y * 128, blockIdx.x * BN,
                      A_g, lda, B_g, K, bias, Cf, ldc, Ch);
}

// ============================================================
// gru_tile: one 128x96 tile of Ghh = h @ Wh3^T + fused GRU epilogue.
// 512 threads, warp grid 4M x 4N (warp tile 32 x 24 = [r8|z8|n8]), MI=2, NI=3.
// ============================================================
__device__ __forceinline__ void gru_tile(
    const half* __restrict__ A_g,      // hprev fp16 [BB,512]
    const half* __restrict__ gx,       // Gx slab [BB,1536]
    const float* __restrict__ hprev32,
    float* __restrict__ hnew32,
    half* __restrict__ hnew16,
    int mbk, int nbk)
{
    constexpr int SS = 72;
    constexpr int MI = 2;
    constexpr int NI = 3;
    constexpr int ABYT = 128 * SS * 2;
    constexpr int BBYT = 96 * SS * 2;
    constexpr int BUF = ABYT + BBYT;
    constexpr int nc = HH >> 6;

    extern __shared__ char smem[];
    const uint32_t sb = smem_u32(smem);

    const int tid = threadIdx.x;
    const int wid = tid >> 5, lane = tid & 31;
    const int wm = wid & 3, wn = wid >> 2;
    const int gr = lane >> 2, tq = lane & 3;
    const int aro = (lane & 7) + ((lane >> 3) & 1) * 8;
    const int aco = (lane >> 4) * 8;
    const int bro = ((lane >> 4) & 1) * 8 + (lane & 7);
    const int bko = ((lane >> 3) & 1) * 8;
    const int b2ro = 16 + (lane & 7);
    const int b2ko = ((lane >> 3) & 1) * 8;

    const long m0 = (long)mbk * 128;
    const int  n0 = nbk * 96;
    const half* B_g = g_Wh3;

    float acc[MI][NI][4];
#pragma unroll
    for (int mi = 0; mi < MI; ++mi)
#pragma unroll
        for (int ni = 0; ni < NI; ++ni)
#pragma unroll
            for (int q = 0; q < 4; ++q) acc[mi][ni][q] = 0.0f;

    auto load_chunk = [&](int ch) {
        const int k0 = ch << 6;
        const uint32_t base = sb + (ch % 3) * BUF;
#pragma unroll
        for (int it = 0; it < 2; ++it) {
            int e = tid + it * 512;
            int row = e >> 3, seg = e & 7;
            cpa16(base + (uint32_t)(row * SS + seg * 8) * 2,
                  A_g + (m0 + row) * (long)HH + k0 + seg * 8);
        }
#pragma unroll
        for (int it = 0; it < 2; ++it) {
            int e = tid + it * 512;
            if (e < 96 * 8) {
                int row = e >> 3, seg = e & 7;
                cpa16(base + ABYT + (uint32_t)(row * SS + seg * 8) * 2,
                      B_g + (long)(n0 + row) * HH + k0 + seg * 8);
            }
        }
    };

    load_chunk(0); cpa_commit();
    load_chunk(1); cpa_commit();

    for (int ch = 0; ch < nc; ++ch) {
        cpa_wait1();
        __syncthreads();
        if (ch + 2 < nc) load_chunk(ch + 2);
        cpa_commit();

        const uint32_t aBase = sb + (ch % 3) * BUF;
        const uint32_t bBase = aBase + ABYT;

#pragma unroll
        for (int k16 = 0; k16 < 4; ++k16) {
            const int kk = k16 * 16;
            uint32_t af[MI][4], bf[NI][2];
#pragma unroll
            for (int mi = 0; mi < MI; ++mi)
                ldsm_x4(af[mi], aBase + (uint32_t)((wm * 32 + mi * 16 + aro) * SS + kk + aco) * 2);
            ldsm_x4(&bf[0][0], bBase + (uint32_t)((wn * 24 + bro) * SS + kk + bko) * 2);
            ldsm_x2(&bf[2][0], bBase + (uint32_t)((wn * 24 + b2ro) * SS + kk + b2ko) * 2);
#pragma unroll
            for (int mi = 0; mi < MI; ++mi)
#pragma unroll
                for (int ni = 0; ni < NI; ++ni)
                    mma16(acc[mi][ni], af[mi], bf[ni]);
        }
    }

    const int jb = 8 * (4 * nbk + wn);
    const int j0 = jb + 2 * tq;
    const float2 bn2 = *(const float2*)(g_bhhn + j0);

#pragma unroll
    for (int mi = 0; mi < MI; ++mi) {
#pragma unroll
        for (int h2 = 0; h2 < 2; ++h2) {
            const long m = m0 + wm * 32 + mi * 16 + gr + h2 * 8;
            const half* gp = gx + m * NG3 + n0 + wn * 24 + 2 * tq;
            float2 gxr = __half22float2(*(const __half2*)(gp));
            float2 gxz = __half22float2(*(const __half2*)(gp + 8));
            float2 gxn = __half22float2(*(const __half2*)(gp + 16));
            float2 hp = *(const float2*)(hprev32 + m * HH + j0);
            const int q0 = h2 * 2, q1 = q0 + 1;

            float r0 = sigf(acc[mi][0][q0] + gxr.x);
            float r1 = sigf(acc[mi][0][q1] + gxr.y);
            float z0 = sigf(acc[mi][1][q0] + gxz.x);
            float z1 = sigf(acc[mi][1][q1] + gxz.y);
            float nv0 = tanhf(gxn.x + r0 * (acc[mi][2][q0] + bn2.x));
            float nv1 = tanhf(gxn.y + r1 * (acc[mi][2][q1] + bn2.y));
            float h0 = (1.0f - z0) * nv0 + z0 * hp.x;
            float h1 = (1.0f - z1) * nv1 + z1 * hp.y;

            *(float2*)(hnew32 + m * HH + j0) = make_float2(h0, h1);
            __half2 ph = __floats2half2_rn(h0, h1);
            *(uint32_t*)(hnew16 + m * HH + j0) = *(uint32_t*)&ph;
        }
    }
}

// ============================================================
// Fused step: gru (512 CTAs) + pipelined decoder/Gx tail-fill.
// bid: [0,512) gru(t) | [512,640) Wm1(t-1) | [640,672) Wm2(t-2)
//      [672,864) Gx(t+4), PAIRED m-blocks | [864,896) Wm3(t-3)
// ============================================================
__global__ void __launch_bounds__(512, 2)
step_fused(int t,
           const half* __restrict__ hin,
           half* __restrict__ hout,
           const float* __restrict__ hprev32,
           float* __restrict__ hnew32,
           const float* __restrict__ bm1,
           const float* __restrict__ bm2,
           const float* __restrict__ bm3,
           float* __restrict__ out)
{
    const int bid = blockIdx.x;
    if (bid < 512) {
        gru_tile(hin, g_Gx + (size_t)(t - 1) * BB * NG3, hprev32, hnew32, hout,
                 bid >> 4, bid & 15);
    } else if (bid < 640) {
        if (t < 2) return;
        int i = bid - 512;
        dec_tile<128, 1>((long)(t - 2) * BB + (long)(i >> 2) * 128, (i & 3) * 128,
                         g_Hd, HH, g_Wm1, HH, bm1, nullptr, HH, g_P1);
    } else if (bid < 672) {
        if (t < 3) return;
        int i = bid - 640;
        dec_tile<64, 1>((long)(t - 3) * BB + (long)i * 128, 0,
                        g_P1, HH, g_Wm2, HH, bm2, nullptr, AA, g_P2);
    } else if (bid < 864) {
        if (t < 2 || t > 123) return;
        int i = bid - 672;                    // 192 CTAs: 16 m-pairs x 12 n
        long mb = (long)(i / 12) * 2;
        int  nb = i % 12;
        dec_tile<128, 0>((long)(t + 3) * BB + mb * 128, nb * 128,
                         g_X, AA, g_Wix, AA, g_gxbias, nullptr, NG3, g_Gx);
        __syncthreads();   // all warps done with smem before re-filling buffers
        dec_tile<128, 0>((long)(t + 3) * BB + (mb + 1) * 128, nb * 128,
                         g_X, AA, g_Wix, AA, g_gxbias, nullptr, NG3, g_Gx);
    } else {
        if (t < 4) return;
        int i = bid - 864;
        dec_tile<64, 3>((long)(t - 4) * BB + (long)i * 128, 0,
                        g_P2, AA, g_Wm3, AA, bm3, out, 0, nullptr);
    }
}

// ============================================================
// Orchestration
// ============================================================
extern "C" void kernel_launch(void* const* d_in, const int* in_sizes, int n_in,
                              void* d_out, int out_size)
{
    const float* latent = (const float*)d_in[0];
    const float* target = (const float*)d_in[1];
    const float* Wd1 = (const float*)d_in[2];
    const float* bd1 = (const float*)d_in[3];
    const float* Wd2 = (const float*)d_in[4];
    const float* bd2 = (const float*)d_in[5];
    const float* Wd3 = (const float*)d_in[6];
    const float* bd3 = (const float*)d_in[7];
    const float* Wih = (const float*)d_in[8];
    const float* Whh = (const float*)d_in[9];
    const float* bih = (const float*)d_in[10];
    const float* bhh = (const float*)d_in[11];
    const float* Wm1 = (const float*)d_in[12];
    const float* bm1 = (const float*)d_in[13];
    const float* Wm2 = (const float*)d_in[14];
    const float* bm2 = (const float*)d_in[15];
    const float* Wm3 = (const float*)d_in[16];
    const float* bm3 = (const float*)d_in[17];
    float* out = (float*)d_out;

#define SYM(v, s) cudaGetSymbolAddress((void**)&v, s)
    half *Hd, *P1, *P2, *X, *Gx, *H0, *t1, *t2, *L;
    half *Wh3, *Wix, *Wd1h, *Wd2h, *Wd3h, *Wm1h, *Wm2h, *Wm3h;
    float *h32a, *h32b, *gxbias, *bhhn;
    SYM(Hd, g_Hd); SYM(P1, g_P1); SYM(P2, g_P2); SYM(X, g_X); SYM(Gx, g_Gx);
    SYM(H0, g_H0); SYM(t1, g_t1); SYM(t2, g_t2); SYM(L, g_L);
    SYM(Wh3, g_Wh3); SYM(Wix, g_Wix);
    SYM(Wd1h, g_Wd1); SYM(Wd2h, g_Wd2); SYM(Wd3h, g_Wd3);
    SYM(Wm1h, g_Wm1); SYM(Wm2h, g_Wm2); SYM(Wm3h, g_Wm3);
    SYM(h32a, g_h32a); SYM(h32b, g_h32b); SYM(gxbias, g_gxbias); SYM(bhhn, g_bhhn);
#undef SYM

    constexpr int SM128 = 3 * (128 * 72 * 2 + 128 * 72 * 2);   // 110592
    constexpr int SM64  = 3 * (128 * 72 * 2 + 64 * 72 * 2);    // 82944
    constexpr int SMF   = SM128;
    cudaFuncSetAttribute(mma_gemm<128, 0>, cudaFuncAttributeMaxDynamicSharedMemorySize, SM128);
    cudaFuncSetAttribute(mma_gemm<128, 1>, cudaFuncAttributeMaxDynamicSharedMemorySize, SM128);
    cudaFuncSetAttribute(mma_gemm<128, 2>, cudaFuncAttributeMaxDynamicSharedMemorySize, SM128);
    cudaFuncSetAttribute(mma_gemm<64, 1>,  cudaFuncAttributeMaxDynamicSharedMemorySize, SM64);
    cudaFuncSetAttribute(mma_gemm<64, 3>,  cudaFuncAttributeMaxDynamicSharedMemorySize, SM64);
    cudaFuncSetAttribute(step_fused,       cudaFuncAttributeMaxDynamicSharedMemorySize, SMF);

    // ---- setup (4th launch = fused step for ncu profiling) ----
    build_X<<<(int)((M2 * AA) / 256), 256>>>(target, X);                       // 1
    build_Wh3<<<(NG3 * HH + 255) / 256, 256>>>(Whh, Wh3);                      // 2
    build_bhhn<<<(HH + 255) / 256, 256>>>(bhh, bhhn);                          // 3
    // 4: dummy fused step (profiling target). Every output slab it writes is
    // recomputed by a later real launch in this same call.
    step_fused<<<896, 512, SMF>>>(10, Hd + (size_t)8 * BB * HH,
                                  Hd + (size_t)9 * BB * HH,
                                  h32a, h32b, bm1, bm2, bm3, out);

    build_Wix<<<(NG3 * AA + 255) / 256, 256>>>(Wih, Wix);
    build_gxbias<<<(NG3 + 255) / 256, 256>>>(bih, bhh, gxbias);
    fill_bos_out<<<(BB * AA) / 256, 256>>>(out);
    tohalf<<<(BB * LAT + 255) / 256, 256>>>(latent, L, BB * LAT);
    tohalf<<<(HH * LAT + 255) / 256, 256>>>(Wd1, Wd1h, HH * LAT);
    tohalf<<<(HH * HH + 255) / 256, 256>>>(Wd2, Wd2h, HH * HH);
    tohalf<<<(HH * HH + 255) / 256, 256>>>(Wd3, Wd3h, HH * HH);
    tohalf<<<(HH * HH + 255) / 256, 256>>>(Wm1, Wm1h, HH * HH);
    tohalf<<<(AA * HH + 255) / 256, 256>>>(Wm2, Wm2h, AA * HH);
    tohalf<<<(AA * AA + 255) / 256, 256>>>(Wm3, Wm3h, AA * AA);

    // ---- Gx slabs 1..5 upfront (steps 1-5); rest pipelined in-step ----
    mma_gemm<128, 0><<<dim3(NG3 / 128, 5 * BB / 128), 512, SM128>>>(
        0, X, AA, Wix, AA, gxbias, nullptr, NG3, Gx);

    // ---- h0 = Wd3(tanh(Wd2(tanh(Wd1(latent))))) ----
    mma_gemm<128, 1><<<dim3(HH / 128, BB / 128), 512, SM128>>>(
        0, L, LAT, Wd1h, LAT, bd1, nullptr, HH, t1);
    mma_gemm<128, 1><<<dim3(HH / 128, BB / 128), 512, SM128>>>(
        0, t1, HH, Wd2h, HH, bd2, nullptr, HH, t2);
    mma_gemm<128, 2><<<dim3(HH / 128, BB / 128), 512, SM128>>>(
        0, t2, HH, Wd3h, HH, bd3, h32a, HH, H0);

    // ---- sequential GRU with fused decoder/Gx tail-fill ----
    float* hp32 = h32a;
    float* hn32 = h32b;
    for (int t = 1; t < LL; ++t) {
        const half* hin = (t == 1) ? H0 : Hd + (size_t)(t - 2) * BB * HH;
        step_fused<<<896, 512, SMF>>>(t, hin,
                                      Hd + (size_t)(t - 1) * BB * HH,
                                      hp32, hn32, bm1, bm2, bm3, out);
        float* tmp = hp32; hp32 = hn32; hn32 = tmp;
    }

    // ---- drain: Wm1 slab 127; Wm2 slabs 126-127; Wm3 slabs 125-127 ----
    mma_gemm<128, 1><<<dim3(HH / 128, BB / 128), 512, SM128>>>(
        (long)126 * BB, Hd, HH, Wm1h, HH, bm1, nullptr, HH, P1);
    mma_gemm<64, 1><<<dim3(1, 2 * BB / 128), 512, SM64>>>(
        (long)125 * BB, P1, HH, Wm2h, HH, bm2, nullptr, AA, P2);
    mma_gemm<64, 3><<<dim3(1, 3 * BB / 128), 512, SM64>>>(
        (long)124 * BB, P2, AA, Wm3h, AA, bm3, out, 0, nullptr);
}